// round 16
// baseline (speedup 1.0000x reference)
#include <cuda_runtime.h>
#include <cuda_fp16.h>
#include <math.h>

#define NA 10000
#define NE 320000
#define F  128
#define F3 (3*F)
#define NRBF 20
#define TT 3
#define NK 2048
#define ABI 16
#define API (ABI/2)
#define ABF 8            // atoms/block in fused field+mix
#define APF (ABF/2)

typedef unsigned long long ull;

// ---------------- scratch (static device globals; no allocation) -------------
__device__ float g_q[NA*F];
__device__ float g_mu[NA*F3];
__device__ float g_dmu[NA*F3];
__device__ float g_E[NA*3];
__device__ float g_x[NA*F3];
__device__ float  g_tabV[TT*NK*F3];   // filter value at knot k (fp32)
__device__ __half g_tabS[TT*NK*F3];   // slope v[k+1]-v[k] (fp16)
__device__ float g_dir[NE*3];
__device__ int   g_k0[NE];
__device__ float g_fr[NE];
__device__ int   g_cnt[NA];
__device__ int   g_starts[NA+1];
__device__ int   g_cursor[NA];
__device__ int   g_perm[NE];

__device__ __forceinline__ float silu_f(float v) {
    return v * (1.0f / (1.0f + __expf(-v)));
}

// ---- packed f32x2 helpers ----
__device__ __forceinline__ ull pk2(float lo, float hi) {
    ull r; asm("mov.b64 %0, {%1,%2};" : "=l"(r) : "f"(lo), "f"(hi)); return r;
}
__device__ __forceinline__ void unpk2(ull v, float& lo, float& hi) {
    asm("mov.b64 {%0,%1}, %2;" : "=f"(lo), "=f"(hi) : "l"(v));
}
__device__ __forceinline__ ull ffma2(ull a, ull b, ull c) {
    ull d; asm("fma.rn.f32x2 %0, %1, %2, %3;" : "=l"(d) : "l"(a), "l"(b), "l"(c));
    return d;
}

// ---------------- init ------------------------------------------------------
__global__ void k_init(const int* __restrict__ zn, const int* __restrict__ idx_m,
                       const float* __restrict__ e_field, const float* __restrict__ emb,
                       int n) {
    int i = blockIdx.x;
    int f = threadIdx.x;
    if (i >= n) return;
    int z = zn[i];
    g_q[i*F + f] = emb[z*F + f];
    g_mu[i*F3 + f]       = 0.0f;
    g_mu[i*F3 + F + f]   = 0.0f;
    g_mu[i*F3 + 2*F + f] = 0.0f;
    if (f < 3) g_E[i*3 + f] = e_field[idx_m[i]*3 + f];
}

// ---------------- edge precompute: dir, table coords ------------------------
__global__ void k_edge(const float* __restrict__ r_ij, int ne) {
    int e = blockIdx.x * blockDim.x + threadIdx.x;
    if (e >= ne) return;
    float x0 = r_ij[e*3+0], x1 = r_ij[e*3+1], x2 = r_ij[e*3+2];
    float d = sqrtf(x0*x0 + x1*x1 + x2*x2);
    float inv = 1.0f / d;
    g_dir[e*3+0] = x0*inv;
    g_dir[e*3+1] = x1*inv;
    g_dir[e*3+2] = x2*inv;
    float u = d * ((float)(NK-1) / 5.0f);
    u = fminf(u, (float)(NK-1));
    int k0 = min((int)u, NK-2);
    g_k0[e] = k0;
    g_fr[e] = u - (float)k0;
}

// ---------------- filter table build ----------------------------------------
__global__ void k_tab(const float* __restrict__ filt_W, const float* __restrict__ filt_b) {
    __shared__ float ph[2][NRBF];
    __shared__ float fcs[2];
    int b = blockIdx.x;
    int t = b / (NK-1);
    int k = b % (NK-1);
    int c = threadIdx.x;  // 0..383
    const float h = 5.0f / (float)(NK-1);
    const float w = 5.0f / 19.0f;
    if (c < 2*NRBF) {
        int s = c / NRBF, r = c % NRBF;
        float d = (float)(k + s) * h;
        float tt = (d - w * (float)r) / w;
        ph[s][r] = __expf(-0.5f * tt * tt);
    }
    if (c >= 2*NRBF && c < 2*NRBF + 2) {
        int s = c - 2*NRBF;
        int kk = k + s;
        float d = (float)kk * h;
        fcs[s] = (kk >= NK-1) ? 0.0f : 0.5f * (__cosf(d * 0.6283185307179586f) + 1.0f);
    }
    __syncthreads();
    float bb = filt_b[t*F3 + c];
    float a0 = bb, a1 = bb;
#pragma unroll
    for (int r = 0; r < NRBF; r++) {
        float wv = filt_W[r * (TT*F3) + t*F3 + c];
        a0 = fmaf(ph[0][r], wv, a0);
        a1 = fmaf(ph[1][r], wv, a1);
    }
    float v0 = a0 * fcs[0];
    float v1 = a1 * fcs[1];
    size_t idx = ((size_t)(t*NK + k))*F3 + c;
    g_tabV[idx] = v0;
    g_tabS[idx] = __float2half_rn(v1 - v0);
}

// ---------------- counting sort of edges by idx_i ---------------------------
__global__ void k_zero(int n) {
    int i = blockIdx.x * blockDim.x + threadIdx.x;
    if (i < n) g_cnt[i] = 0;
}
__global__ void k_hist(const int* __restrict__ idx_i, int ne) {
    int e = blockIdx.x * blockDim.x + threadIdx.x;
    if (e < ne) atomicAdd(&g_cnt[idx_i[e]], 1);
}
__global__ void k_scan(int n) {
    __shared__ int ss[1024];
    int tid = threadIdx.x;
    int chunk = (n + 1023) >> 10;
    int beg = tid * chunk;
    int end = min(beg + chunk, n);
    int s = 0;
    for (int i = beg; i < end; i++) s += g_cnt[i];
    ss[tid] = s;
    __syncthreads();
    for (int off = 1; off < 1024; off <<= 1) {
        int v = (tid >= off) ? ss[tid - off] : 0;
        __syncthreads();
        ss[tid] += v;
        __syncthreads();
    }
    int base = (tid == 0) ? 0 : ss[tid - 1];
    for (int i = beg; i < end; i++) {
        g_starts[i] = base;
        g_cursor[i] = base;
        base += g_cnt[i];
    }
    if (tid == 1023) g_starts[n] = ss[1023];
}
__global__ void k_scatter(const int* __restrict__ idx_i, int ne) {
    int e = blockIdx.x * blockDim.x + threadIdx.x;
    if (e < ne) {
        int p = atomicAdd(&g_cursor[idx_i[e]], 1);
        g_perm[p] = e;
    }
}

// ---------------- inter: x = silu(q@W1+b1)@W2+b2  (R9 config: A=16, 128thr) -
__global__ void __launch_bounds__(128) k_inter(
        const float* __restrict__ W1, const float* __restrict__ b1,
        const float* __restrict__ W2, const float* __restrict__ b2, int n) {
    __shared__ __align__(16) float sq[F][ABI];
    int f = threadIdx.x;
    int a0 = blockIdx.x * ABI;
#pragma unroll
    for (int a = 0; a < ABI; a++) {
        int at = a0 + a;
        int atc = (at < n) ? at : 0;
        sq[f][a] = g_q[atc*F + f];
    }
    __syncthreads();
    ull acc[API];
    {
        float bb = b1[f];
        ull bb2 = pk2(bb, bb);
#pragma unroll
        for (int p = 0; p < API; p++) acc[p] = bb2;
#pragma unroll 4
        for (int k = 0; k < F; k++) {
            float w = W1[k*F + f];
            ull w2 = pk2(w, w);
            const ulonglong2* row = (const ulonglong2*)sq[k];
#pragma unroll
            for (int v = 0; v < API/2; v++) {
                ulonglong2 rv = row[v];
                acc[2*v]   = ffma2(rv.x, w2, acc[2*v]);
                acc[2*v+1] = ffma2(rv.y, w2, acc[2*v+1]);
            }
        }
    }
    __syncthreads();
#pragma unroll
    for (int p = 0; p < API; p++) {
        float lo, hi; unpk2(acc[p], lo, hi);
        sq[f][2*p]   = silu_f(lo);
        sq[f][2*p+1] = silu_f(hi);
    }
    __syncthreads();
#pragma unroll
    for (int c = 0; c < 3; c++) {
        float cb = b2[c*F + f];
        ull acc2[API];
        ull cb2 = pk2(cb, cb);
#pragma unroll
        for (int p = 0; p < API; p++) acc2[p] = cb2;
#pragma unroll 4
        for (int k = 0; k < F; k++) {
            float w = W2[k*F3 + c*F + f];
            ull w2 = pk2(w, w);
            const ulonglong2* row = (const ulonglong2*)sq[k];
#pragma unroll
            for (int v = 0; v < API/2; v++) {
                ulonglong2 rv = row[v];
                acc2[2*v]   = ffma2(rv.x, w2, acc2[2*v]);
                acc2[2*v+1] = ffma2(rv.y, w2, acc2[2*v+1]);
            }
        }
#pragma unroll
        for (int p = 0; p < API; p++) {
            float lo, hi; unpk2(acc2[p], lo, hi);
            int at = a0 + 2*p;
            if (at < n)     g_x[(size_t)at*F3 + c*F + f]     = lo;
            if (at + 1 < n) g_x[(size_t)(at+1)*F3 + c*F + f] = hi;
        }
    }
}

// ---------------- message passing: v+slope table ----------------------------
__global__ void __launch_bounds__(128) k_msg(
        const int* __restrict__ idx_j, int t, int n) {
    __shared__ int   sj[128], sk0[128];
    __shared__ float sfr[128], sd0[128], sd1[128], sd2[128];
    int i = blockIdx.x;
    int f = threadIdx.x;
    if (i >= n) return;
    const float*  __restrict__ tabV = g_tabV + (size_t)t * NK * F3;
    const __half* __restrict__ tabS = g_tabS + (size_t)t * NK * F3;
    int nb = g_starts[i], nend = g_starts[i+1];
    float dq = 0.0f, dm0 = 0.0f, dm1 = 0.0f, dm2 = 0.0f;

    for (int base = nb; base < nend; base += 128) {
        int cnt = min(128, nend - base);
        __syncthreads();
        if (f < cnt) {
            int e = g_perm[base + f];
            sj[f]  = idx_j[e];
            sk0[f] = g_k0[e];
            sfr[f] = g_fr[e];
            sd0[f] = g_dir[e*3+0];
            sd1[f] = g_dir[e*3+1];
            sd2[f] = g_dir[e*3+2];
        }
        __syncthreads();
        for (int k = 0; k < cnt; k++) {
            int j = sj[k];
            size_t rr = (size_t)sk0[k] * F3;
            float fr = sfr[k];
            float fq = fmaf(fr, __half2float(tabS[rr + f]),       tabV[rr + f]);
            float fR = fmaf(fr, __half2float(tabS[rr + F + f]),   tabV[rr + F + f]);
            float fM = fmaf(fr, __half2float(tabS[rr + 2*F + f]), tabV[rr + 2*F + f]);
            const float* xr = g_x  + (size_t)j * F3;
            const float* mr = g_mu + (size_t)j * F3;
            dq = fmaf(fq, xr[f], dq);
            float dR = fR * xr[F + f];
            float dM = fM * xr[2*F + f];
            dm0 = fmaf(dR, sd0[k], fmaf(dM, mr[f], dm0));
            dm1 = fmaf(dR, sd1[k], fmaf(dM, mr[F + f], dm1));
            dm2 = fmaf(dR, sd2[k], fmaf(dM, mr[2*F + f], dm2));
        }
    }
    g_q[i*F + f] += dq;
    g_dmu[i*F3 + f]       = dm0;
    g_dmu[i*F3 + F + f]   = dm1;
    g_dmu[i*F3 + 2*F + f] = dm2;
}

// ---------------- fused field + mix (A=8) -----------------------------------
// Field phase updates mu in shared; mix phase consumes it directly (no global
// mu round-trip between the two ops).
__global__ void __launch_bounds__(128) k_fieldmix(
        const float* __restrict__ fsW1, const float* __restrict__ fsb1,
        const float* __restrict__ fsW2, const float* __restrict__ fsb2,
        const float* __restrict__ fvW,
        const float* __restrict__ muW,  const float* __restrict__ mW1,
        const float* __restrict__ mb1,  const float* __restrict__ mW2,
        const float* __restrict__ mb2,  int n) {
    __shared__ __align__(16) float cs[2*F][ABF];    // rows 0..F-1: q (later h2); F..2F-1: vn
    __shared__ __align__(16) float smu[3][F][ABF];  // mu (field-updated in place)
    __shared__ __align__(16) float hs[F][ABF];      // h (field MLP hidden)
    __shared__ float sE[ABF][3];
    int f = threadIdx.x;
    int a0 = blockIdx.x * ABF;

    // stage q, mu+dmu, E
#pragma unroll
    for (int a = 0; a < ABF; a++) {
        int at = a0 + a;
        int atc = (at < n) ? at : 0;
        cs[f][a] = g_q[atc*F + f];
#pragma unroll
        for (int kv = 0; kv < 3; kv++)
            smu[kv][f][a] = g_mu[(size_t)atc*F3 + kv*F + f] + g_dmu[(size_t)atc*F3 + kv*F + f];
    }
    if (f < ABF*3) {
        int a = f / 3, c = f % 3;
        int at = a0 + a;
        sE[a][c] = (at < n) ? g_E[at*3 + c] : 0.0f;
    }
    __syncthreads();

    // ---- FIELD phase ----
    // h = silu(q @ fsW1 + fsb1)
    {
        ull acc[APF];
        float bb = fsb1[f];
        ull bb2 = pk2(bb, bb);
#pragma unroll
        for (int p = 0; p < APF; p++) acc[p] = bb2;
#pragma unroll 4
        for (int k = 0; k < F; k++) {
            float w = fsW1[k*F + f];
            ull w2 = pk2(w, w);
            const ulonglong2* row = (const ulonglong2*)cs[k];
#pragma unroll
            for (int v = 0; v < APF/2; v++) {
                ulonglong2 rv = row[v];
                acc[2*v]   = ffma2(rv.x, w2, acc[2*v]);
                acc[2*v+1] = ffma2(rv.y, w2, acc[2*v+1]);
            }
        }
#pragma unroll
        for (int p = 0; p < APF; p++) {
            float lo, hi; unpk2(acc[p], lo, hi);
            hs[f][2*p]   = silu_f(lo);
            hs[f][2*p+1] = silu_f(hi);
        }
    }
    __syncthreads();
    // a_s = h @ fsW2 + fsb2 ; a_v = mu @ fvW
    {
        ull as2[APF];
        float bb = fsb2[f];
        ull bb2 = pk2(bb, bb);
#pragma unroll
        for (int p = 0; p < APF; p++) as2[p] = bb2;
#pragma unroll 4
        for (int k = 0; k < F; k++) {
            float w = fsW2[k*F + f];
            ull w2 = pk2(w, w);
            const ulonglong2* row = (const ulonglong2*)hs[k];
#pragma unroll
            for (int v = 0; v < APF/2; v++) {
                ulonglong2 rv = row[v];
                as2[2*v]   = ffma2(rv.x, w2, as2[2*v]);
                as2[2*v+1] = ffma2(rv.y, w2, as2[2*v+1]);
            }
        }
        ull av2[3][APF];
#pragma unroll
        for (int kv = 0; kv < 3; kv++)
#pragma unroll
            for (int p = 0; p < APF; p++) av2[kv][p] = 0ull;
#pragma unroll 2
        for (int c = 0; c < F; c++) {
            float w = fvW[c*F + f];
            ull w2 = pk2(w, w);
#pragma unroll
            for (int kv = 0; kv < 3; kv++) {
                const ulonglong2* row = (const ulonglong2*)smu[kv][c];
#pragma unroll
                for (int v = 0; v < APF/2; v++) {
                    ulonglong2 rv = row[v];
                    av2[kv][2*v]   = ffma2(rv.x, w2, av2[kv][2*v]);
                    av2[kv][2*v+1] = ffma2(rv.y, w2, av2[kv][2*v+1]);
                }
            }
        }
        __syncthreads();   // all reads of smu done before in-place update
#pragma unroll
        for (int p = 0; p < APF; p++) {
            float as_l, as_h; unpk2(as2[p], as_l, as_h);
            float a0l, a0h, a1l, a1h, a2l, a2h;
            unpk2(av2[0][p], a0l, a0h);
            unpk2(av2[1][p], a1l, a1h);
            unpk2(av2[2][p], a2l, a2h);
#pragma unroll
            for (int lane = 0; lane < 2; lane++) {
                int a = 2*p + lane;
                float asv = lane ? as_h : as_l;
                float v0 = lane ? a0h : a0l;
                float v1 = lane ? a1h : a1l;
                float v2 = lane ? a2h : a2l;
                float E0 = sE[a][0], E1 = sE[a][1], E2 = sE[a][2];
                float dot = v0*E0 + v1*E1 + v2*E2;
                smu[0][f][a] += asv*E0 - dot*v0;
                smu[1][f][a] += asv*E1 - dot*v1;
                smu[2][f][a] += asv*E2 - dot*v2;
            }
        }
    }
    __syncthreads();

    // ---- MIX phase ----
    ull Wc2[3][APF];
    ull sdot2[APF];
    {
        ull V2[3][APF];
#pragma unroll
        for (int kv = 0; kv < 3; kv++)
#pragma unroll
            for (int p = 0; p < APF; p++) { V2[kv][p] = 0ull; Wc2[kv][p] = 0ull; }
#pragma unroll 2
        for (int c = 0; c < F; c++) {
            float wv = muW[c*2*F + f];
            float ww = muW[c*2*F + F + f];
            ull wv2 = pk2(wv, wv);
            ull ww2 = pk2(ww, ww);
#pragma unroll
            for (int kv = 0; kv < 3; kv++) {
                const ulonglong2* row = (const ulonglong2*)smu[kv][c];
#pragma unroll
                for (int v = 0; v < APF/2; v++) {
                    ulonglong2 rv = row[v];
                    V2[kv][2*v]    = ffma2(rv.x, wv2, V2[kv][2*v]);
                    V2[kv][2*v+1]  = ffma2(rv.y, wv2, V2[kv][2*v+1]);
                    Wc2[kv][2*v]   = ffma2(rv.x, ww2, Wc2[kv][2*v]);
                    Wc2[kv][2*v+1] = ffma2(rv.y, ww2, Wc2[kv][2*v+1]);
                }
            }
        }
#pragma unroll
        for (int p = 0; p < APF; p++) {
            float v0l, v0h, v1l, v1h, v2l, v2h;
            unpk2(V2[0][p], v0l, v0h);
            unpk2(V2[1][p], v1l, v1h);
            unpk2(V2[2][p], v2l, v2h);
            float w0l, w0h, w1l, w1h, w2l, w2h;
            unpk2(Wc2[0][p], w0l, w0h);
            unpk2(Wc2[1][p], w1l, w1h);
            unpk2(Wc2[2][p], w2l, w2h);
            float vnl = sqrtf(v0l*v0l + v1l*v1l + v2l*v2l + 1e-8f);
            float vnh = sqrtf(v0h*v0h + v1h*v1h + v2h*v2h + 1e-8f);
            cs[F + f][2*p]   = vnl;
            cs[F + f][2*p+1] = vnh;
            sdot2[p] = pk2(v0l*w0l + v1l*w1l + v2l*w2l,
                           v0h*w0h + v1h*w1h + v2h*w2h);
        }
    }
    __syncthreads();
    // h2 = silu(ctx @ mW1 + mb1), ctx = [q | vn] (2F)
    ull acc[APF];
    {
        float bb = mb1[f];
        ull bb2 = pk2(bb, bb);
#pragma unroll
        for (int p = 0; p < APF; p++) acc[p] = bb2;
#pragma unroll 4
        for (int k = 0; k < 2*F; k++) {
            float w = mW1[k*F + f];
            ull w2 = pk2(w, w);
            const ulonglong2* row = (const ulonglong2*)cs[k];
#pragma unroll
            for (int v = 0; v < APF/2; v++) {
                ulonglong2 rv = row[v];
                acc[2*v]   = ffma2(rv.x, w2, acc[2*v]);
                acc[2*v+1] = ffma2(rv.y, w2, acc[2*v+1]);
            }
        }
    }
    __syncthreads();
#pragma unroll
    for (int p = 0; p < APF; p++) {
        float lo, hi; unpk2(acc[p], lo, hi);
        cs[f][2*p]   = silu_f(lo);
        cs[f][2*p+1] = silu_f(hi);
    }
    __syncthreads();
    // y chunks
    ull y0_2[APF];
#pragma unroll
    for (int c = 0; c < 3; c++) {
        float cb = mb2[c*F + f];
        ull accY[APF];
        ull cb2 = pk2(cb, cb);
#pragma unroll
        for (int p = 0; p < APF; p++) accY[p] = cb2;
#pragma unroll 4
        for (int k = 0; k < F; k++) {
            float w = mW2[k*F3 + c*F + f];
            ull w2 = pk2(w, w);
            const ulonglong2* row = (const ulonglong2*)cs[k];
#pragma unroll
            for (int v = 0; v < APF/2; v++) {
                ulonglong2 rv = row[v];
                accY[2*v]   = ffma2(rv.x, w2, accY[2*v]);
                accY[2*v+1] = ffma2(rv.y, w2, accY[2*v+1]);
            }
        }
        if (c == 0) {
#pragma unroll
            for (int p = 0; p < APF; p++) y0_2[p] = accY[p];
        } else if (c == 1) {
#pragma unroll
            for (int p = 0; p < APF; p++) {
                float y1l, y1h; unpk2(accY[p], y1l, y1h);
                float w0l, w0h, w1l, w1h, w2l, w2h;
                unpk2(Wc2[0][p], w0l, w0h);
                unpk2(Wc2[1][p], w1l, w1h);
                unpk2(Wc2[2][p], w2l, w2h);
                int at = a0 + 2*p;
                if (at < n) {
                    g_mu[(size_t)at*F3 + f]       = smu[0][f][2*p] + y1l*w0l;
                    g_mu[(size_t)at*F3 + F + f]   = smu[1][f][2*p] + y1l*w1l;
                    g_mu[(size_t)at*F3 + 2*F + f] = smu[2][f][2*p] + y1l*w2l;
                }
                if (at + 1 < n) {
                    g_mu[(size_t)(at+1)*F3 + f]       = smu[0][f][2*p+1] + y1h*w0h;
                    g_mu[(size_t)(at+1)*F3 + F + f]   = smu[1][f][2*p+1] + y1h*w1h;
                    g_mu[(size_t)(at+1)*F3 + 2*F + f] = smu[2][f][2*p+1] + y1h*w2h;
                }
            }
        } else {
#pragma unroll
            for (int p = 0; p < APF; p++) {
                float y2l, y2h; unpk2(accY[p], y2l, y2h);
                float y0l, y0h; unpk2(y0_2[p], y0l, y0h);
                float sdl, sdh; unpk2(sdot2[p], sdl, sdh);
                int at = a0 + 2*p;
                if (at < n)     g_q[(size_t)at*F + f]     += y0l + y2l*sdl;
                if (at + 1 < n) g_q[(size_t)(at+1)*F + f] += y0h + y2h*sdh;
            }
        }
    }
}

// ---------------- pack output [N,4,F] ---------------------------------------
__global__ void k_pack(float* __restrict__ out, int n) {
    int i = blockIdx.x;
    int f = threadIdx.x;
    if (i >= n) return;
    out[i*4*F + f] = g_q[i*F + f];
#pragma unroll
    for (int kv = 0; kv < 3; kv++)
        out[i*4*F + (1+kv)*F + f] = g_mu[i*F3 + kv*F + f];
}

// ---------------- launch -----------------------------------------------------
extern "C" void kernel_launch(void* const* d_in, const int* in_sizes, int n_in,
                              void* d_out, int out_size) {
    const int*   zn      = (const int*)  d_in[0];
    const float* r_ij    = (const float*)d_in[1];
    const int*   idx_i   = (const int*)  d_in[2];
    const int*   idx_j   = (const int*)  d_in[3];
    const int*   idx_m   = (const int*)  d_in[4];
    const float* e_field = (const float*)d_in[5];
    const float* emb     = (const float*)d_in[6];
    const float* filt_W  = (const float*)d_in[7];
    const float* filt_b  = (const float*)d_in[8];
    const float* iW1     = (const float*)d_in[9];
    const float* ib1     = (const float*)d_in[10];
    const float* iW2     = (const float*)d_in[11];
    const float* ib2     = (const float*)d_in[12];
    const float* fsW1    = (const float*)d_in[13];
    const float* fsb1    = (const float*)d_in[14];
    const float* fsW2    = (const float*)d_in[15];
    const float* fsb2    = (const float*)d_in[16];
    const float* fvW     = (const float*)d_in[17];
    const float* mmuW    = (const float*)d_in[18];
    const float* mW1     = (const float*)d_in[19];
    const float* mb1     = (const float*)d_in[20];
    const float* mW2     = (const float*)d_in[21];
    const float* mb2     = (const float*)d_in[22];

    int n  = in_sizes[0];   // 10000
    int ne = in_sizes[2];   // 320000
    int nblkI = (n + ABI - 1) / ABI;
    int nblkF = (n + ABF - 1) / ABF;

    // k_inter(t=0) stays the 4th launch so ncu keeps profiling it.
    k_init<<<n, F>>>(zn, idx_m, e_field, emb, n);
    k_zero<<<(n + 255) / 256, 256>>>(n);
    k_hist<<<(ne + 255) / 256, 256>>>(idx_i, ne);
    k_inter<<<nblkI, F>>>(iW1, ib1, iW2, ib2, n);          // t = 0
    k_scan<<<1, 1024>>>(n);
    k_scatter<<<(ne + 255) / 256, 256>>>(idx_i, ne);
    k_edge<<<(ne + 255) / 256, 256>>>(r_ij, ne);
    k_tab<<<TT*(NK-1), F3>>>(filt_W, filt_b);

    for (int t = 0; t < TT; t++) {
        if (t > 0)
            k_inter<<<nblkI, F>>>(iW1 + t*F*F, ib1 + t*F,
                                  iW2 + t*F*F3, ib2 + t*F3, n);
        k_msg<<<n, F>>>(idx_j, t, n);
        k_fieldmix<<<nblkF, F>>>(fsW1 + t*F*F, fsb1 + t*F,
                                 fsW2 + t*F*F, fsb2 + t*F,
                                 fvW + t*F*F,
                                 mmuW + t*F*2*F, mW1 + t*2*F*F, mb1 + t*F,
                                 mW2 + t*F*F3, mb2 + t*F3, n);
    }
    k_pack<<<n, F>>>((float*)d_out, n);
}

// round 17
// speedup vs baseline: 1.1248x; 1.1248x over previous
#include <cuda_runtime.h>
#include <cuda_fp16.h>
#include <math.h>

#define NA 10000
#define NE 320000
#define F  128
#define F3 (3*F)
#define NRBF 20
#define TT 3
#define NK 2048          // table knots per t
#define ABI 16
#define API (ABI/2)
#define ABF 8
#define APF (ABF/2)
#define ABM 8
#define APM (ABM/2)

typedef unsigned long long ull;

// ---------------- scratch (static device globals; no allocation) -------------
__device__ float g_q[NA*F];
__device__ float g_mu[NA*F3];
__device__ float g_dmu[NA*F3];
__device__ float g_E[NA*3];
__device__ float g_x[NA*F3];
__device__ float  g_tabV[TT*NK*F3];   // filter value at knot k (fp32)
__device__ __half g_tabS[TT*NK*F3];   // slope v[k+1]-v[k] (fp16)
__device__ float g_dir[NE*3];
__device__ int   g_k0[NE];
__device__ float g_fr[NE];
__device__ int   g_cnt[NA];
__device__ int   g_starts[NA+1];
__device__ int   g_cursor[NA];
__device__ int   g_perm[NE];

__device__ __forceinline__ float silu_f(float v) {
    return v * (1.0f / (1.0f + __expf(-v)));
}

// ---- packed f32x2 helpers ----
__device__ __forceinline__ ull pk2(float lo, float hi) {
    ull r; asm("mov.b64 %0, {%1,%2};" : "=l"(r) : "f"(lo), "f"(hi)); return r;
}
__device__ __forceinline__ void unpk2(ull v, float& lo, float& hi) {
    asm("mov.b64 {%0,%1}, %2;" : "=f"(lo), "=f"(hi) : "l"(v));
}
__device__ __forceinline__ ull ffma2(ull a, ull b, ull c) {
    ull d; asm("fma.rn.f32x2 %0, %1, %2, %3;" : "=l"(d) : "l"(a), "l"(b), "l"(c));
    return d;
}

// ---------------- init ------------------------------------------------------
__global__ void k_init(const int* __restrict__ zn, const int* __restrict__ idx_m,
                       const float* __restrict__ e_field, const float* __restrict__ emb,
                       int n) {
    int i = blockIdx.x;
    int f = threadIdx.x;
    if (i >= n) return;
    int z = zn[i];
    g_q[i*F + f] = emb[z*F + f];
    g_mu[i*F3 + f]       = 0.0f;
    g_mu[i*F3 + F + f]   = 0.0f;
    g_mu[i*F3 + 2*F + f] = 0.0f;
    if (f < 3) g_E[i*3 + f] = e_field[idx_m[i]*3 + f];
}

// ---------------- edge precompute: dir, table coords ------------------------
__global__ void k_edge(const float* __restrict__ r_ij, int ne) {
    int e = blockIdx.x * blockDim.x + threadIdx.x;
    if (e >= ne) return;
    float x0 = r_ij[e*3+0], x1 = r_ij[e*3+1], x2 = r_ij[e*3+2];
    float d = sqrtf(x0*x0 + x1*x1 + x2*x2);
    float inv = 1.0f / d;
    g_dir[e*3+0] = x0*inv;
    g_dir[e*3+1] = x1*inv;
    g_dir[e*3+2] = x2*inv;
    float u = d * ((float)(NK-1) / 5.0f);
    u = fminf(u, (float)(NK-1));
    int k0 = min((int)u, NK-2);
    g_k0[e] = k0;
    g_fr[e] = u - (float)k0;
}

// ---------------- filter table build ----------------------------------------
__global__ void k_tab(const float* __restrict__ filt_W, const float* __restrict__ filt_b) {
    __shared__ float ph[2][NRBF];
    __shared__ float fcs[2];
    int b = blockIdx.x;
    int t = b / (NK-1);
    int k = b % (NK-1);
    int c = threadIdx.x;  // 0..383
    const float h = 5.0f / (float)(NK-1);
    const float w = 5.0f / 19.0f;
    if (c < 2*NRBF) {
        int s = c / NRBF, r = c % NRBF;
        float d = (float)(k + s) * h;
        float tt = (d - w * (float)r) / w;
        ph[s][r] = __expf(-0.5f * tt * tt);
    }
    if (c >= 2*NRBF && c < 2*NRBF + 2) {
        int s = c - 2*NRBF;
        int kk = k + s;
        float d = (float)kk * h;
        fcs[s] = (kk >= NK-1) ? 0.0f : 0.5f * (__cosf(d * 0.6283185307179586f) + 1.0f);
    }
    __syncthreads();
    float bb = filt_b[t*F3 + c];
    float a0 = bb, a1 = bb;
#pragma unroll
    for (int r = 0; r < NRBF; r++) {
        float wv = filt_W[r * (TT*F3) + t*F3 + c];
        a0 = fmaf(ph[0][r], wv, a0);
        a1 = fmaf(ph[1][r], wv, a1);
    }
    float v0 = a0 * fcs[0];
    float v1 = a1 * fcs[1];
    size_t idx = ((size_t)(t*NK + k))*F3 + c;
    g_tabV[idx] = v0;
    g_tabS[idx] = __float2half_rn(v1 - v0);
}

// ---------------- counting sort of edges by idx_i ---------------------------
__global__ void k_zero(int n) {
    int i = blockIdx.x * blockDim.x + threadIdx.x;
    if (i < n) g_cnt[i] = 0;
}
__global__ void k_hist(const int* __restrict__ idx_i, int ne) {
    int e = blockIdx.x * blockDim.x + threadIdx.x;
    if (e < ne) atomicAdd(&g_cnt[idx_i[e]], 1);
}
__global__ void k_scan(int n) {
    __shared__ int ss[1024];
    int tid = threadIdx.x;
    int chunk = (n + 1023) >> 10;
    int beg = tid * chunk;
    int end = min(beg + chunk, n);
    int s = 0;
    for (int i = beg; i < end; i++) s += g_cnt[i];
    ss[tid] = s;
    __syncthreads();
    for (int off = 1; off < 1024; off <<= 1) {
        int v = (tid >= off) ? ss[tid - off] : 0;
        __syncthreads();
        ss[tid] += v;
        __syncthreads();
    }
    int base = (tid == 0) ? 0 : ss[tid - 1];
    for (int i = beg; i < end; i++) {
        g_starts[i] = base;
        g_cursor[i] = base;
        base += g_cnt[i];
    }
    if (tid == 1023) g_starts[n] = ss[1023];
}
__global__ void k_scatter(const int* __restrict__ idx_i, int ne) {
    int e = blockIdx.x * blockDim.x + threadIdx.x;
    if (e < ne) {
        int p = atomicAdd(&g_cursor[idx_i[e]], 1);
        g_perm[p] = e;
    }
}

// ---------------- inter: x = silu(q@W1+b1)@W2+b2  (A=16, weight unroll 8) ---
__global__ void __launch_bounds__(128) k_inter(
        const float* __restrict__ W1, const float* __restrict__ b1,
        const float* __restrict__ W2, const float* __restrict__ b2, int n) {
    __shared__ __align__(16) float sq[F][ABI];
    int f = threadIdx.x;
    int a0 = blockIdx.x * ABI;
#pragma unroll
    for (int a = 0; a < ABI; a++) {
        int at = a0 + a;
        int atc = (at < n) ? at : 0;
        sq[f][a] = g_q[atc*F + f];
    }
    __syncthreads();
    ull acc[API];
    {
        float bb = b1[f];
        ull bb2 = pk2(bb, bb);
#pragma unroll
        for (int p = 0; p < API; p++) acc[p] = bb2;
#pragma unroll 8
        for (int k = 0; k < F; k++) {
            float w = W1[k*F + f];
            ull w2 = pk2(w, w);
            const ulonglong2* row = (const ulonglong2*)sq[k];
#pragma unroll
            for (int v = 0; v < API/2; v++) {
                ulonglong2 rv = row[v];
                acc[2*v]   = ffma2(rv.x, w2, acc[2*v]);
                acc[2*v+1] = ffma2(rv.y, w2, acc[2*v+1]);
            }
        }
    }
    __syncthreads();
#pragma unroll
    for (int p = 0; p < API; p++) {
        float lo, hi; unpk2(acc[p], lo, hi);
        sq[f][2*p]   = silu_f(lo);
        sq[f][2*p+1] = silu_f(hi);
    }
    __syncthreads();
#pragma unroll
    for (int c = 0; c < 3; c++) {
        float cb = b2[c*F + f];
        ull acc2[API];
        ull cb2 = pk2(cb, cb);
#pragma unroll
        for (int p = 0; p < API; p++) acc2[p] = cb2;
#pragma unroll 8
        for (int k = 0; k < F; k++) {
            float w = W2[k*F3 + c*F + f];
            ull w2 = pk2(w, w);
            const ulonglong2* row = (const ulonglong2*)sq[k];
#pragma unroll
            for (int v = 0; v < API/2; v++) {
                ulonglong2 rv = row[v];
                acc2[2*v]   = ffma2(rv.x, w2, acc2[2*v]);
                acc2[2*v+1] = ffma2(rv.y, w2, acc2[2*v+1]);
            }
        }
#pragma unroll
        for (int p = 0; p < API; p++) {
            float lo, hi; unpk2(acc2[p], lo, hi);
            int at = a0 + 2*p;
            if (at < n)     g_x[(size_t)at*F3 + c*F + f]     = lo;
            if (at + 1 < n) g_x[(size_t)(at+1)*F3 + c*F + f] = hi;
        }
    }
}

// ---------------- message passing: v+slope table ----------------------------
__global__ void __launch_bounds__(128) k_msg(
        const int* __restrict__ idx_j, int t, int n) {
    __shared__ int   sj[128], sk0[128];
    __shared__ float sfr[128], sd0[128], sd1[128], sd2[128];
    int i = blockIdx.x;
    int f = threadIdx.x;
    if (i >= n) return;
    const float*  __restrict__ tabV = g_tabV + (size_t)t * NK * F3;
    const __half* __restrict__ tabS = g_tabS + (size_t)t * NK * F3;
    int nb = g_starts[i], nend = g_starts[i+1];
    float dq = 0.0f, dm0 = 0.0f, dm1 = 0.0f, dm2 = 0.0f;

    for (int base = nb; base < nend; base += 128) {
        int cnt = min(128, nend - base);
        __syncthreads();
        if (f < cnt) {
            int e = g_perm[base + f];
            sj[f]  = idx_j[e];
            sk0[f] = g_k0[e];
            sfr[f] = g_fr[e];
            sd0[f] = g_dir[e*3+0];
            sd1[f] = g_dir[e*3+1];
            sd2[f] = g_dir[e*3+2];
        }
        __syncthreads();
        for (int k = 0; k < cnt; k++) {
            int j = sj[k];
            size_t rr = (size_t)sk0[k] * F3;
            float fr = sfr[k];
            float fq = fmaf(fr, __half2float(tabS[rr + f]),       tabV[rr + f]);
            float fR = fmaf(fr, __half2float(tabS[rr + F + f]),   tabV[rr + F + f]);
            float fM = fmaf(fr, __half2float(tabS[rr + 2*F + f]), tabV[rr + 2*F + f]);
            const float* xr = g_x  + (size_t)j * F3;
            const float* mr = g_mu + (size_t)j * F3;
            dq = fmaf(fq, xr[f], dq);
            float dR = fR * xr[F + f];
            float dM = fM * xr[2*F + f];
            dm0 = fmaf(dR, sd0[k], fmaf(dM, mr[f], dm0));
            dm1 = fmaf(dR, sd1[k], fmaf(dM, mr[F + f], dm1));
            dm2 = fmaf(dR, sd2[k], fmaf(dM, mr[2*F + f], dm2));
        }
    }
    g_q[i*F + f] += dq;
    g_dmu[i*F3 + f]       = dm0;
    g_dmu[i*F3 + F + f]   = dm1;
    g_dmu[i*F3 + 2*F + f] = dm2;
}

// ---------------- field interaction (A=8, folds dmu) ------------------------
__global__ void __launch_bounds__(128) k_field(
        const float* __restrict__ sW1, const float* __restrict__ sb1,
        const float* __restrict__ sW2, const float* __restrict__ sb2,
        const float* __restrict__ vW, int n) {
    __shared__ __align__(16) float sq[F][ABF];
    __shared__ __align__(16) float smu[3][F][ABF];
    __shared__ float sE[ABF][3];
    int f = threadIdx.x;
    int a0 = blockIdx.x * ABF;
#pragma unroll
    for (int a = 0; a < ABF; a++) {
        int at = a0 + a;
        int atc = (at < n) ? at : 0;
        sq[f][a] = g_q[atc*F + f];
#pragma unroll
        for (int kv = 0; kv < 3; kv++)
            smu[kv][f][a] = g_mu[(size_t)atc*F3 + kv*F + f] + g_dmu[(size_t)atc*F3 + kv*F + f];
    }
    if (f < ABF*3) {
        int a = f / 3, c = f % 3;
        int at = a0 + a;
        sE[a][c] = (at < n) ? g_E[at*3 + c] : 0.0f;
    }
    __syncthreads();
    ull acc[APF];
    {
        float bb = sb1[f];
        ull bb2 = pk2(bb, bb);
#pragma unroll
        for (int p = 0; p < APF; p++) acc[p] = bb2;
#pragma unroll 4
        for (int k = 0; k < F; k++) {
            float w = sW1[k*F + f];
            ull w2 = pk2(w, w);
            const ulonglong2* row = (const ulonglong2*)sq[k];
#pragma unroll
            for (int v = 0; v < APF/2; v++) {
                ulonglong2 rv = row[v];
                acc[2*v]   = ffma2(rv.x, w2, acc[2*v]);
                acc[2*v+1] = ffma2(rv.y, w2, acc[2*v+1]);
            }
        }
    }
    __syncthreads();
#pragma unroll
    for (int p = 0; p < APF; p++) {
        float lo, hi; unpk2(acc[p], lo, hi);
        sq[f][2*p]   = silu_f(lo);
        sq[f][2*p+1] = silu_f(hi);
    }
    __syncthreads();
    ull as2[APF];
    {
        float bb = sb2[f];
        ull bb2 = pk2(bb, bb);
#pragma unroll
        for (int p = 0; p < APF; p++) as2[p] = bb2;
#pragma unroll 4
        for (int k = 0; k < F; k++) {
            float w = sW2[k*F + f];
            ull w2 = pk2(w, w);
            const ulonglong2* row = (const ulonglong2*)sq[k];
#pragma unroll
            for (int v = 0; v < APF/2; v++) {
                ulonglong2 rv = row[v];
                as2[2*v]   = ffma2(rv.x, w2, as2[2*v]);
                as2[2*v+1] = ffma2(rv.y, w2, as2[2*v+1]);
            }
        }
    }
    ull av2[3][APF];
#pragma unroll
    for (int kv = 0; kv < 3; kv++)
#pragma unroll
        for (int p = 0; p < APF; p++) av2[kv][p] = 0ull;
#pragma unroll 2
    for (int c = 0; c < F; c++) {
        float w = vW[c*F + f];
        ull w2 = pk2(w, w);
#pragma unroll
        for (int kv = 0; kv < 3; kv++) {
            const ulonglong2* row = (const ulonglong2*)smu[kv][c];
#pragma unroll
            for (int v = 0; v < APF/2; v++) {
                ulonglong2 rv = row[v];
                av2[kv][2*v]   = ffma2(rv.x, w2, av2[kv][2*v]);
                av2[kv][2*v+1] = ffma2(rv.y, w2, av2[kv][2*v+1]);
            }
        }
    }
#pragma unroll
    for (int p = 0; p < APF; p++) {
        float as_l, as_h; unpk2(as2[p], as_l, as_h);
        float a0l, a0h, a1l, a1h, a2l, a2h;
        unpk2(av2[0][p], a0l, a0h);
        unpk2(av2[1][p], a1l, a1h);
        unpk2(av2[2][p], a2l, a2h);
#pragma unroll
        for (int lane = 0; lane < 2; lane++) {
            int a = 2*p + lane;
            int at = a0 + a;
            if (at >= n) continue;
            float asv = lane ? as_h : as_l;
            float v0 = lane ? a0h : a0l;
            float v1 = lane ? a1h : a1l;
            float v2 = lane ? a2h : a2l;
            float E0 = sE[a][0], E1 = sE[a][1], E2 = sE[a][2];
            float dot = v0*E0 + v1*E1 + v2*E2;
            g_mu[(size_t)at*F3 + f]       = smu[0][f][a] + asv*E0 - dot*v0;
            g_mu[(size_t)at*F3 + F + f]   = smu[1][f][a] + asv*E1 - dot*v1;
            g_mu[(size_t)at*F3 + 2*F + f] = smu[2][f][a] + asv*E2 - dot*v2;
        }
    }
}

// ---------------- mixing (A=8) ----------------------------------------------
__global__ void __launch_bounds__(128) k_mix(
        const float* __restrict__ muW, const float* __restrict__ W1,
        const float* __restrict__ b1,  const float* __restrict__ W2,
        const float* __restrict__ b2,  int n) {
    __shared__ __align__(16) float smu[3][F][ABM];
    __shared__ __align__(16) float cs[2*F][ABM];
    int f = threadIdx.x;
    int a0 = blockIdx.x * ABM;
#pragma unroll
    for (int a = 0; a < ABM; a++) {
        int at = a0 + a;
        int atc = (at < n) ? at : 0;
        cs[f][a] = g_q[atc*F + f];
#pragma unroll
        for (int kv = 0; kv < 3; kv++)
            smu[kv][f][a] = g_mu[(size_t)atc*F3 + kv*F + f];
    }
    __syncthreads();
    ull Wc2[3][APM];
    ull sdot2[APM];
    {
        ull V2[3][APM];
#pragma unroll
        for (int kv = 0; kv < 3; kv++)
#pragma unroll
            for (int p = 0; p < APM; p++) { V2[kv][p] = 0ull; Wc2[kv][p] = 0ull; }
#pragma unroll 2
        for (int c = 0; c < F; c++) {
            float wv = muW[c*2*F + f];
            float ww = muW[c*2*F + F + f];
            ull wv2 = pk2(wv, wv);
            ull ww2 = pk2(ww, ww);
#pragma unroll
            for (int kv = 0; kv < 3; kv++) {
                const ulonglong2* row = (const ulonglong2*)smu[kv][c];
#pragma unroll
                for (int v = 0; v < APM/2; v++) {
                    ulonglong2 rv = row[v];
                    V2[kv][2*v]    = ffma2(rv.x, wv2, V2[kv][2*v]);
                    V2[kv][2*v+1]  = ffma2(rv.y, wv2, V2[kv][2*v+1]);
                    Wc2[kv][2*v]   = ffma2(rv.x, ww2, Wc2[kv][2*v]);
                    Wc2[kv][2*v+1] = ffma2(rv.y, ww2, Wc2[kv][2*v+1]);
                }
            }
        }
#pragma unroll
        for (int p = 0; p < APM; p++) {
            float v0l, v0h, v1l, v1h, v2l, v2h;
            unpk2(V2[0][p], v0l, v0h);
            unpk2(V2[1][p], v1l, v1h);
            unpk2(V2[2][p], v2l, v2h);
            float w0l, w0h, w1l, w1h, w2l, w2h;
            unpk2(Wc2[0][p], w0l, w0h);
            unpk2(Wc2[1][p], w1l, w1h);
            unpk2(Wc2[2][p], w2l, w2h);
            float vnl = sqrtf(v0l*v0l + v1l*v1l + v2l*v2l + 1e-8f);
            float vnh = sqrtf(v0h*v0h + v1h*v1h + v2h*v2h + 1e-8f);
            cs[F + f][2*p]   = vnl;
            cs[F + f][2*p+1] = vnh;
            sdot2[p] = pk2(v0l*w0l + v1l*w1l + v2l*w2l,
                           v0h*w0h + v1h*w1h + v2h*w2h);
        }
    }
    __syncthreads();
    ull acc[APM];
    {
        float bb = b1[f];
        ull bb2 = pk2(bb, bb);
#pragma unroll
        for (int p = 0; p < APM; p++) acc[p] = bb2;
#pragma unroll 4
        for (int k = 0; k < 2*F; k++) {
            float w = W1[k*F + f];
            ull w2 = pk2(w, w);
            const ulonglong2* row = (const ulonglong2*)cs[k];
#pragma unroll
            for (int v = 0; v < APM/2; v++) {
                ulonglong2 rv = row[v];
                acc[2*v]   = ffma2(rv.x, w2, acc[2*v]);
                acc[2*v+1] = ffma2(rv.y, w2, acc[2*v+1]);
            }
        }
    }
    __syncthreads();
#pragma unroll
    for (int p = 0; p < APM; p++) {
        float lo, hi; unpk2(acc[p], lo, hi);
        cs[f][2*p]   = silu_f(lo);
        cs[f][2*p+1] = silu_f(hi);
    }
    __syncthreads();
    ull y0_2[APM];
#pragma unroll
    for (int c = 0; c < 3; c++) {
        float cb = b2[c*F + f];
        ull accY[APM];
        ull cb2 = pk2(cb, cb);
#pragma unroll
        for (int p = 0; p < APM; p++) accY[p] = cb2;
#pragma unroll 4
        for (int k = 0; k < F; k++) {
            float w = W2[k*F3 + c*F + f];
            ull w2 = pk2(w, w);
            const ulonglong2* row = (const ulonglong2*)cs[k];
#pragma unroll
            for (int v = 0; v < APM/2; v++) {
                ulonglong2 rv = row[v];
                accY[2*v]   = ffma2(rv.x, w2, accY[2*v]);
                accY[2*v+1] = ffma2(rv.y, w2, accY[2*v+1]);
            }
        }
        if (c == 0) {
#pragma unroll
            for (int p = 0; p < APM; p++) y0_2[p] = accY[p];
        } else if (c == 1) {
#pragma unroll
            for (int p = 0; p < APM; p++) {
                float y1l, y1h; unpk2(accY[p], y1l, y1h);
                float w0l, w0h, w1l, w1h, w2l, w2h;
                unpk2(Wc2[0][p], w0l, w0h);
                unpk2(Wc2[1][p], w1l, w1h);
                unpk2(Wc2[2][p], w2l, w2h);
                int at = a0 + 2*p;
                if (at < n) {
                    g_mu[(size_t)at*F3 + f]       = smu[0][f][2*p] + y1l*w0l;
                    g_mu[(size_t)at*F3 + F + f]   = smu[1][f][2*p] + y1l*w1l;
                    g_mu[(size_t)at*F3 + 2*F + f] = smu[2][f][2*p] + y1l*w2l;
                }
                if (at + 1 < n) {
                    g_mu[(size_t)(at+1)*F3 + f]       = smu[0][f][2*p+1] + y1h*w0h;
                    g_mu[(size_t)(at+1)*F3 + F + f]   = smu[1][f][2*p+1] + y1h*w1h;
                    g_mu[(size_t)(at+1)*F3 + 2*F + f] = smu[2][f][2*p+1] + y1h*w2h;
                }
            }
        } else {
#pragma unroll
            for (int p = 0; p < APM; p++) {
                float y2l, y2h; unpk2(accY[p], y2l, y2h);
                float y0l, y0h; unpk2(y0_2[p], y0l, y0h);
                float sdl, sdh; unpk2(sdot2[p], sdl, sdh);
                int at = a0 + 2*p;
                if (at < n)     g_q[(size_t)at*F + f]     += y0l + y2l*sdl;
                if (at + 1 < n) g_q[(size_t)(at+1)*F + f] += y0h + y2h*sdh;
            }
        }
    }
}

// ---------------- pack output [N,4,F] ---------------------------------------
__global__ void k_pack(float* __restrict__ out, int n) {
    int i = blockIdx.x;
    int f = threadIdx.x;
    if (i >= n) return;
    out[i*4*F + f] = g_q[i*F + f];
#pragma unroll
    for (int kv = 0; kv < 3; kv++)
        out[i*4*F + (1+kv)*F + f] = g_mu[i*F3 + kv*F + f];
}

// ---------------- launch -----------------------------------------------------
extern "C" void kernel_launch(void* const* d_in, const int* in_sizes, int n_in,
                              void* d_out, int out_size) {
    const int*   zn      = (const int*)  d_in[0];
    const float* r_ij    = (const float*)d_in[1];
    const int*   idx_i   = (const int*)  d_in[2];
    const int*   idx_j   = (const int*)  d_in[3];
    const int*   idx_m   = (const int*)  d_in[4];
    const float* e_field = (const float*)d_in[5];
    const float* emb     = (const float*)d_in[6];
    const float* filt_W  = (const float*)d_in[7];
    const float* filt_b  = (const float*)d_in[8];
    const float* iW1     = (const float*)d_in[9];
    const float* ib1     = (const float*)d_in[10];
    const float* iW2     = (const float*)d_in[11];
    const float* ib2     = (const float*)d_in[12];
    const float* fsW1    = (const float*)d_in[13];
    const float* fsb1    = (const float*)d_in[14];
    const float* fsW2    = (const float*)d_in[15];
    const float* fsb2    = (const float*)d_in[16];
    const float* fvW     = (const float*)d_in[17];
    const float* mmuW    = (const float*)d_in[18];
    const float* mW1     = (const float*)d_in[19];
    const float* mb1     = (const float*)d_in[20];
    const float* mW2     = (const float*)d_in[21];
    const float* mb2     = (const float*)d_in[22];

    int n  = in_sizes[0];   // 10000
    int ne = in_sizes[2];   // 320000
    int nblkI = (n + ABI - 1) / ABI;
    int nblkF = (n + ABF - 1) / ABF;
    int nblkM = (n + ABM - 1) / ABM;

    // k_inter(t=0) stays the 4th launch so ncu keeps profiling it.
    k_init<<<n, F>>>(zn, idx_m, e_field, emb, n);
    k_zero<<<(n + 255) / 256, 256>>>(n);
    k_hist<<<(ne + 255) / 256, 256>>>(idx_i, ne);
    k_inter<<<nblkI, F>>>(iW1, ib1, iW2, ib2, n);          // t = 0
    k_scan<<<1, 1024>>>(n);
    k_scatter<<<(ne + 255) / 256, 256>>>(idx_i, ne);
    k_edge<<<(ne + 255) / 256, 256>>>(r_ij, ne);
    k_tab<<<TT*(NK-1), F3>>>(filt_W, filt_b);

    for (int t = 0; t < TT; t++) {
        if (t > 0)
            k_inter<<<nblkI, F>>>(iW1 + t*F*F, ib1 + t*F,
                                  iW2 + t*F*F3, ib2 + t*F3, n);
        k_msg<<<n, F>>>(idx_j, t, n);
        k_field<<<nblkF, F>>>(fsW1 + t*F*F, fsb1 + t*F,
                              fsW2 + t*F*F, fsb2 + t*F,
                              fvW + t*F*F, n);
        k_mix<<<nblkM, F>>>(mmuW + t*F*2*F, mW1 + t*2*F*F, mb1 + t*F,
                            mW2 + t*F*F3, mb2 + t*F3, n);
    }
    k_pack<<<n, F>>>((float*)d_out, n);
}